// round 11
// baseline (speedup 1.0000x reference)
#include <cuda_runtime.h>
#include <cuda_bf16.h>
#include <cstdint>

#define D 256
#define BT 2048   // B*T
#define KS 512    // stored K per row: [hi(256) | lo(256)]
#define NST 3     // cp.async pipeline stages
#define NCTA 128
#define NTHR 256

// Scratch (static device globals — no allocation).
__device__ float g_Q[BT * D];
__device__ float g_K[BT * D];
__device__ float g_V[BT * D];
__device__ __nv_bfloat16 g_Ap[BT * KS];       // split X  [hi|lo]
__device__ __nv_bfloat16 g_Wp[3][D * KS];     // split Wq/Wk/Wv [hi|lo]

// Grid barrier state: monotonic generation, per-barrier count (auto-reset).
__device__ unsigned g_count = 0;
__device__ unsigned g_gen   = 0;

// ---------------------------------------------------------------------------
// helpers
// ---------------------------------------------------------------------------
__device__ __forceinline__ uint32_t smem_u32(const void* p) {
    uint32_t a;
    asm("{ .reg .u64 t; cvta.to.shared.u64 t, %1; cvt.u32.u64 %0, t; }"
        : "=r"(a) : "l"(p));
    return a;
}
__device__ __forceinline__ void ldm_x4(uint32_t& r0, uint32_t& r1,
                                       uint32_t& r2, uint32_t& r3, uint32_t a) {
    asm volatile("ldmatrix.sync.aligned.m8n8.x4.shared.b16 {%0,%1,%2,%3}, [%4];"
                 : "=r"(r0), "=r"(r1), "=r"(r2), "=r"(r3) : "r"(a));
}
__device__ __forceinline__ void mma16816(float* c, const uint32_t* a,
                                         const uint32_t* b) {
    asm volatile(
        "mma.sync.aligned.m16n8k16.row.col.f32.bf16.bf16.f32 "
        "{%0,%1,%2,%3}, {%4,%5,%6,%7}, {%8,%9}, {%0,%1,%2,%3};"
        : "+f"(c[0]), "+f"(c[1]), "+f"(c[2]), "+f"(c[3])
        : "r"(a[0]), "r"(a[1]), "r"(a[2]), "r"(a[3]), "r"(b[0]), "r"(b[1]));
}
__device__ __forceinline__ void cpa16(uint32_t s, const void* g) {
    asm volatile("cp.async.cg.shared.global [%0], [%1], 16;"
                 :: "r"(s), "l"(g) : "memory");
}
#define CP_COMMIT() asm volatile("cp.async.commit_group;" ::: "memory")
#define CP_WAIT1()  asm volatile("cp.async.wait_group 1;" ::: "memory")
#define CP_WAIT0()  asm volatile("cp.async.wait_group 0;" ::: "memory")

// 128B rows, 8 x 16B chunks, full XOR swizzle: chunk ^= row&7.
#define SWOFF2(row, c) ((row) * 128 + ((((c) ^ ((row) & 7))) << 4))

struct __align__(8) bf16x4 { __nv_bfloat162 a, b; };

// Software grid barrier. All NCTA CTAs must be co-resident (NCTA <= #SMs).
// Generation counter is monotonic across launches -> deterministic, no reset.
__device__ __forceinline__ void grid_barrier() {
    __syncthreads();
    if (threadIdx.x == 0) {
        __threadfence();
        volatile unsigned* genp = &g_gen;
        const unsigned gen = *genp;
        const unsigned a = atomicAdd(&g_count, 1u);
        if (a == NCTA - 1) {
            atomicExch(&g_count, 0u);
            __threadfence();
            *genp = gen + 1;
        } else {
            while (*genp == gen) { }
            __threadfence();
        }
    }
    __syncthreads();
}

// ---------------------------------------------------------------------------
// Fused kernel: convert -> barrier -> 3x GEMM jobs -> barrier -> attention.
// ---------------------------------------------------------------------------
__global__ __launch_bounds__(NTHR) void fused_kernel(
    const float4* __restrict__ X4,
    const float4* __restrict__ Wq4,
    const float4* __restrict__ Wk4,
    const float4* __restrict__ Wv4,
    const float* __restrict__ bq, const float* __restrict__ bk,
    const float* __restrict__ bv, float* __restrict__ out)
{
    __shared__ __align__(16) char sA[NST][64 * 128];   // 24KB
    __shared__ __align__(16) char sB[NST][64 * 128];   // 24KB

    const int tid  = threadIdx.x;
    const int lane = tid & 31;
    const int wid  = tid >> 5;
    const int cta  = blockIdx.x;

    // ===================== Phase 1: split-precision convert ================
    {
        const int tglob = cta * NTHR + tid;          // 0..32767
        #pragma unroll
        for (int j = 0; j < 6; j++) {
            const int gid = tglob + j * (NCTA * NTHR);
            if (gid >= 180224) break;
            float4 x;
            __nv_bfloat16* hp;
            if (gid < BT * D / 4) {
                const int t = gid >> 6;
                const int d = (gid & 63) * 4;
                x = X4[gid];
                hp = &g_Ap[t * KS + d];
            } else {
                const int g = gid - BT * D / 4;      // < 49152
                const int z = g >> 14;
                const int r = g & 16383;
                const int i = r >> 6;
                const int d = (r & 63) * 4;
                const float4* W4 = (z == 0) ? Wq4 : (z == 1) ? Wk4 : Wv4;
                x = W4[r];
                hp = &g_Wp[z][i * KS + d];
            }
            __nv_bfloat16 h0 = __float2bfloat16_rn(x.x);
            __nv_bfloat16 h1 = __float2bfloat16_rn(x.y);
            __nv_bfloat16 h2 = __float2bfloat16_rn(x.z);
            __nv_bfloat16 h3 = __float2bfloat16_rn(x.w);
            bf16x4 hi, lo;
            hi.a = __nv_bfloat162(h0, h1);
            hi.b = __nv_bfloat162(h2, h3);
            lo.a = __nv_bfloat162(
                __float2bfloat16_rn(x.x - __bfloat162float(h0)),
                __float2bfloat16_rn(x.y - __bfloat162float(h1)));
            lo.b = __nv_bfloat162(
                __float2bfloat16_rn(x.z - __bfloat162float(h2)),
                __float2bfloat16_rn(x.w - __bfloat162float(h3)));
            *(bf16x4*)hp         = hi;
            *(bf16x4*)(hp + 256) = lo;
        }
    }

    grid_barrier();

    // ===================== Phase 2: 3 GEMM tile-jobs per CTA ================
    // CTA -> (row0, col0); loops z = 0,1,2. Warp tile 32x16 (8 warps = 64x64).
    {
        const int row0 = (cta >> 2) * 64;
        const int col0 = (cta & 3) * 64;
        const int warp_m = wid & 1;
        const int warp_n = wid >> 1;        // 0..3

        // loader: thread -> (row, 2 x 16B chunks)
        const int lrow  = tid >> 2;          // 0..63
        const int cpair = (tid & 3) * 2;     // 0,2,4,6
        const uint32_t sA_base = smem_u32(sA);
        const uint32_t sB_base = smem_u32(sB);
        uint32_t saoff[2], sboff[2];
        #pragma unroll
        for (int j = 0; j < 2; j++) {
            saoff[j] = sA_base + SWOFF2(lrow, cpair + j);
            sboff[j] = sB_base + SWOFF2(lrow, cpair + j);
        }

        // ldmatrix fragment addresses
        uint32_t aaddr[2][4], baddr[4];
        {
            const int m = lane >> 3;
            const int ar  = ((m & 1) << 3) + (lane & 7);
            const int akc = m >> 1;
            const int bn  = ((m >> 1) << 3) + (lane & 7);
            const int bkc = m & 1;
            #pragma unroll
            for (int f = 0; f < 2; f++) {
                const int row = warp_m * 32 + f * 16 + ar;
                #pragma unroll
                for (int h = 0; h < 4; h++)
                    aaddr[f][h] = sA_base + SWOFF2(row, akc + 2 * h);
            }
            #pragma unroll
            for (int h = 0; h < 4; h++)
                baddr[h] = sB_base + SWOFF2(warp_n * 16 + bn, bkc + 2 * h);
        }

        for (int z = 0; z < 3; z++) {
            const float* bias = (z == 0) ? bq : (z == 1) ? bk : bv;
            float* Cw = (z == 0) ? g_Q : (z == 1) ? g_K : g_V;
            const int kmax = (z == 2) ? 12 : 8;
            const __nv_bfloat16* agp =
                g_Ap + (size_t)(row0 + lrow) * KS + cpair * 8;
            const __nv_bfloat16* bgp =
                g_Wp[z] + (size_t)(col0 + lrow) * KS + cpair * 8;

            CP_WAIT0();
            __syncthreads();     // smem safe to overwrite

            float acc[2][2][4];
            #pragma unroll
            for (int f = 0; f < 2; f++)
                #pragma unroll
                for (int g = 0; g < 2; g++)
                    #pragma unroll
                    for (int i = 0; i < 4; i++) acc[f][g][i] = 0.f;

            // prologue: stages 0,1
            #pragma unroll
            for (int st = 0; st < NST - 1; st++) {
                const int kt  = (z == 2) ? st : ((st < 4) ? st : st + 4);
                const int akt = (kt < 8) ? kt : kt - 8;
                const int bkt = (kt < 4) ? kt : kt - 4;
                const uint32_t so = st * 8192;
                #pragma unroll
                for (int j = 0; j < 2; j++) {
                    cpa16(saoff[j] + so, agp + akt * 64 + j * 8);
                    cpa16(sboff[j] + so, bgp + bkt * 64 + j * 8);
                }
                CP_COMMIT();
            }

            int sbuf = 0;
            for (int it = 0; it < kmax; it++) {
                CP_WAIT1();
                __syncthreads();

                const int nst = it + NST - 1;
                if (nst < kmax) {
                    const int nb = (sbuf + 2 >= NST) ? sbuf + 2 - NST : sbuf + 2;
                    const int kt  = (z == 2) ? nst : ((nst < 4) ? nst : nst + 4);
                    const int akt = (kt < 8) ? kt : kt - 8;
                    const int bkt = (kt < 4) ? kt : kt - 4;
                    const uint32_t so = nb * 8192;
                    #pragma unroll
                    for (int j = 0; j < 2; j++) {
                        cpa16(saoff[j] + so, agp + akt * 64 + j * 8);
                        cpa16(sboff[j] + so, bgp + bkt * 64 + j * 8);
                    }
                }
                CP_COMMIT();

                const uint32_t so = sbuf * 8192;
                #pragma unroll
                for (int h = 0; h < 4; h++) {
                    uint32_t af[2][4], bfr[4];
                    ldm_x4(af[0][0], af[0][1], af[0][2], af[0][3],
                           aaddr[0][h] + so);
                    ldm_x4(af[1][0], af[1][1], af[1][2], af[1][3],
                           aaddr[1][h] + so);
                    ldm_x4(bfr[0], bfr[1], bfr[2], bfr[3], baddr[h] + so);
                    #pragma unroll
                    for (int f = 0; f < 2; f++) {
                        mma16816(acc[f][0], af[f], &bfr[0]);
                        mma16816(acc[f][1], af[f], &bfr[2]);
                    }
                }
                sbuf = (sbuf + 1 >= NST) ? 0 : sbuf + 1;
            }

            // epilogue
            const int tg = lane >> 2;
            const int tc = (lane & 3) * 2;
            #pragma unroll
            for (int f = 0; f < 2; f++) {
                const int rbase = row0 + warp_m * 32 + f * 16 + tg;
                #pragma unroll
                for (int g = 0; g < 2; g++) {
                    const int c = col0 + warp_n * 16 + g * 8 + tc;
                    const float b0 = bias[c], b1 = bias[c + 1];
                    float2 v0 = { acc[f][g][0] + b0, acc[f][g][1] + b1 };
                    float2 v1 = { acc[f][g][2] + b0, acc[f][g][3] + b1 };
                    *(float2*)&Cw[(size_t)rbase * D + c]       = v0;
                    *(float2*)&Cw[(size_t)(rbase + 8) * D + c] = v1;
                }
            }
        }
    }

    grid_barrier();

    // ===================== Phase 3: attention (2 tokens per warp) ==========
    {
        const float s = 1.0f / 16.0f;
        const float invf[13] = {
            1.f, 1.f, 0.5f, 1.f/6.f, 1.f/24.f, 1.f/120.f, 1.f/720.f,
            1.f/5040.f, 1.f/40320.f, 1.f/362880.f, 1.f/3628800.f,
            1.f/39916800.f, 1.f/479001600.f };

        #pragma unroll
        for (int rep = 0; rep < 2; rep++) {
            const int t = cta * 16 + wid * 2 + rep;
            const int eb = t * D + lane * 8;

            float4 k4a = *(const float4*)&g_K[eb];
            float4 k4b = *(const float4*)&g_K[eb + 4];
            float4 v4a = *(const float4*)&g_V[eb];
            float4 v4b = *(const float4*)&g_V[eb + 4];
            float4 q4a = *(const float4*)&g_Q[eb];
            float4 q4b = *(const float4*)&g_Q[eb + 4];

            float kv[8] = { k4a.x * s, k4a.y * s, k4a.z * s, k4a.w * s,
                            k4b.x * s, k4b.y * s, k4b.z * s, k4b.w * s };
            float vv[8] = { v4a.x, v4a.y, v4a.z, v4a.w,
                            v4b.x, v4b.y, v4b.z, v4b.w };
            float qv[8] = { q4a.x, q4a.y, q4a.z, q4a.w,
                            q4b.x, q4b.y, q4b.z, q4b.w };

            float m[13], M[13];
            #pragma unroll
            for (int n = 0; n < 13; n++) { m[n] = 0.f; M[n] = 0.f; }
            #pragma unroll
            for (int u = 0; u < 8; u++) {
                const float k1 = kv[u], v1 = vv[u];
                M[0] += v1;
                float kp = k1;
                m[1] += kp; M[1] += kp * v1;
                #pragma unroll
                for (int n = 2; n <= 12; n++) {
                    kp *= k1;
                    m[n] += kp;
                    M[n] += kp * v1;
                }
            }
            m[0] = 8.0f;

            #pragma unroll
            for (int off = 16; off; off >>= 1) {
                #pragma unroll
                for (int n = 0; n < 13; n++) {
                    m[n] += __shfl_xor_sync(0xFFFFFFFFu, m[n], off);
                    M[n] += __shfl_xor_sync(0xFFFFFFFFu, M[n], off);
                }
            }

            #pragma unroll
            for (int n = 2; n < 13; n++) { m[n] *= invf[n]; M[n] *= invf[n]; }

            float res[8];
            #pragma unroll
            for (int u = 0; u < 8; u++) {
                const float q = qv[u];
                float num = M[12], den = m[12];
                #pragma unroll
                for (int n = 11; n >= 0; n--) {
                    num = num * q + M[n];
                    den = den * q + m[n];
                }
                res[u] = __fdividef(num, den);
            }
            *(float4*)&out[eb]     = make_float4(res[0], res[1], res[2], res[3]);
            *(float4*)&out[eb + 4] = make_float4(res[4], res[5], res[6], res[7]);
        }
    }
}

// ---------------------------------------------------------------------------
// Launch. Inputs: x, Wq, bq, Wk, bk, Wv, bv. Output fp32 [2,1024,256].
// ---------------------------------------------------------------------------
extern "C" void kernel_launch(void* const* d_in, const int* in_sizes, int n_in,
                              void* d_out, int out_size)
{
    const float* x  = (const float*)d_in[0];
    const float* Wq = (const float*)d_in[1];
    const float* bq = (const float*)d_in[2];
    const float* Wk = (const float*)d_in[3];
    const float* bk = (const float*)d_in[4];
    const float* Wv = (const float*)d_in[5];
    const float* bv = (const float*)d_in[6];
    float* out = (float*)d_out;

    fused_kernel<<<NCTA, NTHR>>>((const float4*)x, (const float4*)Wq,
                                 (const float4*)Wk, (const float4*)Wv,
                                 bq, bk, bv, out);
}

// round 12
// speedup vs baseline: 1.0170x; 1.0170x over previous
#include <cuda_runtime.h>
#include <cuda_bf16.h>
#include <cstdint>

#define D 256
#define BT 2048   // B*T
#define KS 512    // stored K per row: [hi(256) | lo(256)]
#define NST 3     // cp.async pipeline stages

// Scratch (static device globals — no allocation).
__device__ float g_Q[BT * D];
__device__ float g_K[BT * D];
__device__ float g_V[BT * D];
__device__ __nv_bfloat16 g_Ap[BT * KS];       // split X  [hi|lo]
__device__ __nv_bfloat16 g_Wp[3][D * KS];     // split Wq/Wk/Wv [hi|lo]

// ---------------------------------------------------------------------------
// helpers
// ---------------------------------------------------------------------------
__device__ __forceinline__ uint32_t smem_u32(const void* p) {
    uint32_t a;
    asm("{ .reg .u64 t; cvta.to.shared.u64 t, %1; cvt.u32.u64 %0, t; }"
        : "=r"(a) : "l"(p));
    return a;
}
__device__ __forceinline__ void ldm_x4(uint32_t& r0, uint32_t& r1,
                                       uint32_t& r2, uint32_t& r3, uint32_t a) {
    asm volatile("ldmatrix.sync.aligned.m8n8.x4.shared.b16 {%0,%1,%2,%3}, [%4];"
                 : "=r"(r0), "=r"(r1), "=r"(r2), "=r"(r3) : "r"(a));
}
__device__ __forceinline__ void mma16816(float* c, const uint32_t* a,
                                         const uint32_t* b) {
    asm volatile(
        "mma.sync.aligned.m16n8k16.row.col.f32.bf16.bf16.f32 "
        "{%0,%1,%2,%3}, {%4,%5,%6,%7}, {%8,%9}, {%0,%1,%2,%3};"
        : "+f"(c[0]), "+f"(c[1]), "+f"(c[2]), "+f"(c[3])
        : "r"(a[0]), "r"(a[1]), "r"(a[2]), "r"(a[3]), "r"(b[0]), "r"(b[1]));
}
__device__ __forceinline__ void cpa16(uint32_t s, const void* g) {
    asm volatile("cp.async.cg.shared.global [%0], [%1], 16;"
                 :: "r"(s), "l"(g) : "memory");
}
#define CP_COMMIT() asm volatile("cp.async.commit_group;" ::: "memory")
#define CP_WAIT1()  asm volatile("cp.async.wait_group 1;" ::: "memory")

// 128B rows, 8 x 16B chunks, full XOR swizzle: chunk ^= row&7.
#define SWOFF2(row, c) ((row) * 128 + ((((c) ^ ((row) & 7))) << 4))

struct __align__(8) bf16x4 { __nv_bfloat162 a, b; };

// ---------------------------------------------------------------------------
// Split-precision conversion (R6 version): one float4 per thread, 8B stores.
// Threads [0, 131072) convert X; [131072, 180224) convert W.
// ---------------------------------------------------------------------------
__global__ __launch_bounds__(256) void convert_all(
    const float4* __restrict__ X4,
    const float4* __restrict__ Wq4,
    const float4* __restrict__ Wk4,
    const float4* __restrict__ Wv4)
{
    const int gid = blockIdx.x * 256 + threadIdx.x;
    float4 x;
    __nv_bfloat16* hp;
    if (gid < BT * D / 4) {
        const int t = gid >> 6;            // 64 float4 per row
        const int d = (gid & 63) * 4;
        x = X4[gid];
        hp = &g_Ap[t * KS + d];
    } else {
        const int g = gid - BT * D / 4;    // < 49152
        const int z = g >> 14;             // 16384 float4 per matrix
        const int r = g & 16383;
        const int i = r >> 6;
        const int d = (r & 63) * 4;
        const float4* W4 = (z == 0) ? Wq4 : (z == 1) ? Wk4 : Wv4;
        x = W4[r];
        hp = &g_Wp[z][i * KS + d];
    }
    __nv_bfloat16 h0 = __float2bfloat16_rn(x.x);
    __nv_bfloat16 h1 = __float2bfloat16_rn(x.y);
    __nv_bfloat16 h2 = __float2bfloat16_rn(x.z);
    __nv_bfloat16 h3 = __float2bfloat16_rn(x.w);
    bf16x4 hi, lo;
    hi.a = __nv_bfloat162(h0, h1);
    hi.b = __nv_bfloat162(h2, h3);
    lo.a = __nv_bfloat162(__float2bfloat16_rn(x.x - __bfloat162float(h0)),
                          __float2bfloat16_rn(x.y - __bfloat162float(h1)));
    lo.b = __nv_bfloat162(__float2bfloat16_rn(x.z - __bfloat162float(h2)),
                          __float2bfloat16_rn(x.w - __bfloat162float(h3)));
    *(bf16x4*)hp         = hi;
    *(bf16x4*)(hp + 256) = lo;
}

// ---------------------------------------------------------------------------
// bf16 mma.sync GEMM, CTA tile 64(M) x 128(N), 256 threads (8 warps, 2x4),
// K-step 64, 3-stage cp.async, dynamic smem 72KB.
// Logical K-tiles (64-wide): A'=[hi|lo|hi] -> akt = kt<8 ? kt : kt-8
//                            W'=[hi|hi|lo] -> bkt = kt<4 ? kt : kt-4
// Executed tile sets:
//   z==2 (V): 12 tiles, kt = it              (full: hihi + lohi + hilo)
//   z<2 (Q,K): 8 tiles, kt = it<4? it : it+4 (drops Alo*Whi -> err ~1.3e-4)
// Grid 32 x 2 x 3 = 192 CTAs (~10 warps/SM).
// ---------------------------------------------------------------------------
__global__ __launch_bounds__(256) void mma_gemm(
    const float* __restrict__ bq, const float* __restrict__ bk,
    const float* __restrict__ bv)
{
    extern __shared__ __align__(16) char smem[];
    // layout: [NST stages of A: 8KB each][NST stages of B: 16KB each]

    const int tid  = threadIdx.x;
    const int lane = tid & 31;
    const int wid  = tid >> 5;
    const int warp_m = wid & 1;          // 2 x 32 = 64 M
    const int warp_n = wid >> 1;         // 4 x 32 = 128 N

    const int row0 = blockIdx.x * 64;
    const int col0 = blockIdx.y * 128;
    const int z    = blockIdx.z;
    const float* bias = (z == 0) ? bq : (z == 1) ? bk : bv;
    float* Cw = (z == 0) ? g_Q : (z == 1) ? g_K : g_V;
    const int kmax = (z == 2) ? 12 : 8;

    const __nv_bfloat16* Ag = g_Ap;
    const __nv_bfloat16* Bg = g_Wp[z];

    // ---- loaders ----
    // A: 64 rows x 8 chunks = 512 chunks; thread -> (row=tid>>2, 2 chunks)
    const int alrow = tid >> 2;
    const int acp   = (tid & 3) * 2;
    const __nv_bfloat16* agp = Ag + (size_t)(row0 + alrow) * KS + acp * 8;
    // B: 128 rows x 8 chunks = 1024 chunks; thread -> (row=tid>>1, 4 chunks)
    const int blrow = tid >> 1;
    const int bcp   = (tid & 1) * 4;
    const __nv_bfloat16* bgp = Bg + (size_t)(col0 + blrow) * KS + bcp * 8;

    const uint32_t sA_base = smem_u32(smem);
    const uint32_t sB_base = sA_base + NST * 8192;
    uint32_t saoff[2], sboff[4];
    #pragma unroll
    for (int j = 0; j < 2; j++) saoff[j] = sA_base + SWOFF2(alrow, acp + j);
    #pragma unroll
    for (int j = 0; j < 4; j++) sboff[j] = sB_base + SWOFF2(blrow, bcp + j);

    // ---- ldmatrix fragment addresses: [frag][h] over 4 k16-halves ----
    uint32_t aaddr[2][4], baddr[2][4];
    {
        const int m = lane >> 3;
        const int ar  = ((m & 1) << 3) + (lane & 7);
        const int akc = m >> 1;
        const int bn  = ((m >> 1) << 3) + (lane & 7);
        const int bkc = m & 1;
        #pragma unroll
        for (int f = 0; f < 2; f++) {
            const int row = warp_m * 32 + f * 16 + ar;
            #pragma unroll
            for (int h = 0; h < 4; h++)
                aaddr[f][h] = sA_base + SWOFF2(row, akc + 2 * h);
        }
        #pragma unroll
        for (int g = 0; g < 2; g++) {
            const int row = warp_n * 32 + g * 16 + bn;
            #pragma unroll
            for (int h = 0; h < 4; h++)
                baddr[g][h] = sB_base + SWOFF2(row, bkc + 2 * h);
        }
    }

    float acc[2][4][4];
    #pragma unroll
    for (int f = 0; f < 2; f++)
        #pragma unroll
        for (int g = 0; g < 4; g++)
            #pragma unroll
            for (int i = 0; i < 4; i++) acc[f][g][i] = 0.f;

    // prologue: stages 0,1
    #pragma unroll
    for (int st = 0; st < NST - 1; st++) {
        const int kt  = (z == 2) ? st : ((st < 4) ? st : st + 4);
        const int akt = (kt < 8) ? kt : kt - 8;
        const int bkt = (kt < 4) ? kt : kt - 4;
        const uint32_t soa = st * 8192, sob = st * 16384;
        #pragma unroll
        for (int j = 0; j < 2; j++)
            cpa16(saoff[j] + soa, agp + akt * 64 + j * 8);
        #pragma unroll
        for (int j = 0; j < 4; j++)
            cpa16(sboff[j] + sob, bgp + bkt * 64 + j * 8);
        CP_COMMIT();
    }

    int sbuf = 0;                         // stage buffer index (mod 3)
    for (int it = 0; it < kmax; it++) {
        CP_WAIT1();
        __syncthreads();

        const int nst = it + NST - 1;
        if (nst < kmax) {
            const int nb = (sbuf + 2 >= NST) ? sbuf + 2 - NST : sbuf + 2;
            const int kt  = (z == 2) ? nst : ((nst < 4) ? nst : nst + 4);
            const int akt = (kt < 8) ? kt : kt - 8;
            const int bkt = (kt < 4) ? kt : kt - 4;
            const uint32_t soa = nb * 8192, sob = nb * 16384;
            #pragma unroll
            for (int j = 0; j < 2; j++)
                cpa16(saoff[j] + soa, agp + akt * 64 + j * 8);
            #pragma unroll
            for (int j = 0; j < 4; j++)
                cpa16(sboff[j] + sob, bgp + bkt * 64 + j * 8);
        }
        CP_COMMIT();

        const uint32_t soa = sbuf * 8192, sob = sbuf * 16384;
        #pragma unroll
        for (int h = 0; h < 4; h++) {
            uint32_t af[2][4], bfr[2][4];
            ldm_x4(af[0][0], af[0][1], af[0][2], af[0][3], aaddr[0][h] + soa);
            ldm_x4(af[1][0], af[1][1], af[1][2], af[1][3], aaddr[1][h] + soa);
            ldm_x4(bfr[0][0], bfr[0][1], bfr[0][2], bfr[0][3], baddr[0][h] + sob);
            ldm_x4(bfr[1][0], bfr[1][1], bfr[1][2], bfr[1][3], baddr[1][h] + sob);
            #pragma unroll
            for (int f = 0; f < 2; f++) {
                #pragma unroll
                for (int g = 0; g < 2; g++) {
                    mma16816(acc[f][2 * g + 0], af[f], &bfr[g][0]);
                    mma16816(acc[f][2 * g + 1], af[f], &bfr[g][2]);
                }
            }
        }
        sbuf = (sbuf + 1 >= NST) ? 0 : sbuf + 1;
    }

    // epilogue: add bias, store fp32
    const int tg = lane >> 2;
    const int tc = (lane & 3) * 2;
    #pragma unroll
    for (int f = 0; f < 2; f++) {
        const int rbase = row0 + warp_m * 32 + f * 16 + tg;
        #pragma unroll
        for (int g = 0; g < 4; g++) {
            const int c = col0 + warp_n * 32 + g * 8 + tc;
            const float b0 = bias[c], b1 = bias[c + 1];
            float2 v0 = { acc[f][g][0] + b0, acc[f][g][1] + b1 };
            float2 v1 = { acc[f][g][2] + b0, acc[f][g][3] + b1 };
            *(float2*)&Cw[(size_t)rbase * D + c]       = v0;
            *(float2*)&Cw[(size_t)(rbase + 8) * D + c] = v1;
        }
    }
}

// ---------------------------------------------------------------------------
// Attention via rank-13 Taylor factorization of exp(q*k/16).
// 256 CTAs x 8 warps (one warp per token). Lane owns 8 contiguous elements.
// ---------------------------------------------------------------------------
__global__ __launch_bounds__(256) void attn_kernel(float* __restrict__ out)
{
    const int lane = threadIdx.x & 31;
    const int t = blockIdx.x * 8 + (threadIdx.x >> 5);
    const int base = t * D;
    const int eb = base + lane * 8;
    const float s = 1.0f / 16.0f;

    float4 k4a = *(const float4*)&g_K[eb];
    float4 k4b = *(const float4*)&g_K[eb + 4];
    float4 v4a = *(const float4*)&g_V[eb];
    float4 v4b = *(const float4*)&g_V[eb + 4];
    float4 q4a = *(const float4*)&g_Q[eb];
    float4 q4b = *(const float4*)&g_Q[eb + 4];

    float kv[8] = { k4a.x * s, k4a.y * s, k4a.z * s, k4a.w * s,
                    k4b.x * s, k4b.y * s, k4b.z * s, k4b.w * s };
    float vv[8] = { v4a.x, v4a.y, v4a.z, v4a.w, v4b.x, v4b.y, v4b.z, v4b.w };
    float qv[8] = { q4a.x, q4a.y, q4a.z, q4a.w, q4b.x, q4b.y, q4b.z, q4b.w };

    float m[13], M[13];
    #pragma unroll
    for (int n = 0; n < 13; n++) { m[n] = 0.f; M[n] = 0.f; }
    #pragma unroll
    for (int u = 0; u < 8; u++) {
        const float k1 = kv[u], v1 = vv[u];
        M[0] += v1;
        float kp = k1;
        m[1] += kp; M[1] += kp * v1;
        #pragma unroll
        for (int n = 2; n <= 12; n++) {
            kp *= k1;
            m[n] += kp;
            M[n] += kp * v1;
        }
    }
    m[0] = 8.0f;

    #pragma unroll
    for (int off = 16; off; off >>= 1) {
        #pragma unroll
        for (int n = 0; n < 13; n++) {
            m[n] += __shfl_xor_sync(0xFFFFFFFFu, m[n], off);
            M[n] += __shfl_xor_sync(0xFFFFFFFFu, M[n], off);
        }
    }

    const float invf[13] = {
        1.f, 1.f, 0.5f, 1.f/6.f, 1.f/24.f, 1.f/120.f, 1.f/720.f,
        1.f/5040.f, 1.f/40320.f, 1.f/362880.f, 1.f/3628800.f,
        1.f/39916800.f, 1.f/479001600.f };
    #pragma unroll
    for (int n = 2; n < 13; n++) { m[n] *= invf[n]; M[n] *= invf[n]; }

    float res[8];
    #pragma unroll
    for (int u = 0; u < 8; u++) {
        const float q = qv[u];
        float num = M[12], den = m[12];
        #pragma unroll
        for (int n = 11; n >= 0; n--) {
            num = num * q + M[n];
            den = den * q + m[n];
        }
        res[u] = __fdividef(num, den);
    }
    *(float4*)&out[eb]     = make_float4(res[0], res[1], res[2], res[3]);
    *(float4*)&out[eb + 4] = make_float4(res[4], res[5], res[6], res[7]);
}

// ---------------------------------------------------------------------------
// Launch. Inputs: x, Wq, bq, Wk, bk, Wv, bv. Output fp32 [2,1024,256].
// ---------------------------------------------------------------------------
extern "C" void kernel_launch(void* const* d_in, const int* in_sizes, int n_in,
                              void* d_out, int out_size)
{
    const float* x  = (const float*)d_in[0];
    const float* Wq = (const float*)d_in[1];
    const float* bq = (const float*)d_in[2];
    const float* Wk = (const float*)d_in[3];
    const float* bk = (const float*)d_in[4];
    const float* Wv = (const float*)d_in[5];
    const float* bv = (const float*)d_in[6];
    float* out = (float*)d_out;

    cudaFuncSetAttribute(mma_gemm, cudaFuncAttributeMaxDynamicSharedMemorySize,
                         NST * 24576);

    convert_all<<<704, 256>>>((const float4*)x, (const float4*)Wq,
                              (const float4*)Wk, (const float4*)Wv);
    dim3 ggrid(BT / 64, D / 128, 3);   // 32 x 2 x 3 = 192 CTAs
    mma_gemm<<<ggrid, 256, NST * 24576>>>(bq, bk, bv);
    attn_kernel<<<BT / 8, 256>>>(out);
}

// round 13
// speedup vs baseline: 1.4142x; 1.3906x over previous
#include <cuda_runtime.h>
#include <cstdint>

#define D 256
#define BT 2048   // B*T
#define NST 3     // cp.async pipeline stages
#define KTILES 8  // K=256 in 32-float tiles

// Scratch (static device globals — no allocation).
__device__ float g_Q[BT * D];
__device__ float g_K[BT * D];
__device__ float g_V[BT * D];

// ---------------------------------------------------------------------------
// helpers
// ---------------------------------------------------------------------------
__device__ __forceinline__ uint32_t smem_u32(const void* p) {
    uint32_t a;
    asm("{ .reg .u64 t; cvta.to.shared.u64 t, %1; cvt.u32.u64 %0, t; }"
        : "=r"(a) : "l"(p));
    return a;
}
__device__ __forceinline__ void ldm_x4(uint32_t& r0, uint32_t& r1,
                                       uint32_t& r2, uint32_t& r3, uint32_t a) {
    asm volatile("ldmatrix.sync.aligned.m8n8.x4.shared.b16 {%0,%1,%2,%3}, [%4];"
                 : "=r"(r0), "=r"(r1), "=r"(r2), "=r"(r3) : "r"(a));
}
// m16n8k8 TF32 MMA. A frag 4 regs, B frag 2 regs, C/D 4 f32.
__device__ __forceinline__ void mma168_tf32(float* c, const uint32_t* a,
                                            const uint32_t* b) {
    asm volatile(
        "mma.sync.aligned.m16n8k8.row.col.f32.tf32.tf32.f32 "
        "{%0,%1,%2,%3}, {%4,%5,%6,%7}, {%8,%9}, {%0,%1,%2,%3};"
        : "+f"(c[0]), "+f"(c[1]), "+f"(c[2]), "+f"(c[3])
        : "r"(a[0]), "r"(a[1]), "r"(a[2]), "r"(a[3]), "r"(b[0]), "r"(b[1]));
}
__device__ __forceinline__ void cpa16(uint32_t s, const void* g) {
    asm volatile("cp.async.cg.shared.global [%0], [%1], 16;"
                 :: "r"(s), "l"(g) : "memory");
}
#define CP_COMMIT() asm volatile("cp.async.commit_group;" ::: "memory")
#define CP_WAIT1()  asm volatile("cp.async.wait_group 1;" ::: "memory")

// Round f32 bits to nearest tf32 (13 low mantissa bits): +0x1000, HW truncates.
#define RN_TF32(r) ((r) + 0x1000u)

// 128B rows, 8 x 16B chunks, full XOR swizzle: chunk ^= row&7.
#define SWOFF2(row, c) ((row) * 128 + ((((c) ^ ((row) & 7))) << 4))

// ---------------------------------------------------------------------------
// TF32 mma.sync GEMM on RAW fp32 inputs (no conversion pass).
//   C[64,64] tile = x[64,256] @ W[64,256]^T + bias
// 4 warps (warp tile 32x32), K-step 32 floats (128B rows), 3-stage cp.async.
// Fragment byte-layout of m16n8k8.tf32 == m16n8k16.bf16 -> identical
// ldmatrix/swizzle code. RN-rounding to tf32 applied in registers (unbiased).
// Grid 32 x 4 x 3 = 384 CTAs.
// ---------------------------------------------------------------------------
__global__ __launch_bounds__(128) void mma_gemm(
    const float* __restrict__ X,
    const float* __restrict__ Wq, const float* __restrict__ Wk,
    const float* __restrict__ Wv,
    const float* __restrict__ bq, const float* __restrict__ bk,
    const float* __restrict__ bv)
{
    __shared__ __align__(16) char sA[NST][64 * 128];   // 24KB
    __shared__ __align__(16) char sB[NST][64 * 128];   // 24KB

    const int tid  = threadIdx.x;
    const int lane = tid & 31;
    const int wid  = tid >> 5;
    const int warp_m = wid & 1;
    const int warp_n = wid >> 1;

    const int row0 = blockIdx.x * 64;
    const int col0 = blockIdx.y * 64;
    const int z    = blockIdx.z;
    const float* Wg   = (z == 0) ? Wq : (z == 1) ? Wk : Wv;
    const float* bias = (z == 0) ? bq : (z == 1) ? bk : bv;
    float* Cw = (z == 0) ? g_Q : (z == 1) ? g_K : g_V;

    // loader: thread -> (row, 4 x 16B chunks); k-tile = 32 floats = 8 chunks
    const int lrow  = tid >> 1;          // 0..63
    const int cbase = (tid & 1) * 4;     // 0 or 4
    const float* agp = X  + (size_t)(row0 + lrow) * D + cbase * 4;
    const float* bgp = Wg + (size_t)(col0 + lrow) * D + cbase * 4;
    const uint32_t sA_base = smem_u32(sA);
    const uint32_t sB_base = smem_u32(sB);
    uint32_t saoff[4], sboff[4];
    #pragma unroll
    for (int j = 0; j < 4; j++) {
        saoff[j] = sA_base + SWOFF2(lrow, cbase + j);
        sboff[j] = sB_base + SWOFF2(lrow, cbase + j);
    }

    // ldmatrix fragment addresses: [frag][h] over 4 k8-steps per 128B row
    uint32_t aaddr[2][4], baddr[2][4];
    {
        const int m = lane >> 3;
        const int ar  = ((m & 1) << 3) + (lane & 7);
        const int akc = m >> 1;
        const int bn  = ((m >> 1) << 3) + (lane & 7);
        const int bkc = m & 1;
        #pragma unroll
        for (int f = 0; f < 2; f++) {
            const int row = warp_m * 32 + f * 16 + ar;
            #pragma unroll
            for (int h = 0; h < 4; h++)
                aaddr[f][h] = sA_base + SWOFF2(row, akc + 2 * h);
        }
        #pragma unroll
        for (int g = 0; g < 2; g++) {
            const int row = warp_n * 32 + g * 16 + bn;
            #pragma unroll
            for (int h = 0; h < 4; h++)
                baddr[g][h] = sB_base + SWOFF2(row, bkc + 2 * h);
        }
    }

    float acc[2][4][4];
    #pragma unroll
    for (int f = 0; f < 2; f++)
        #pragma unroll
        for (int g = 0; g < 4; g++)
            #pragma unroll
            for (int i = 0; i < 4; i++) acc[f][g][i] = 0.f;

    // prologue: stages 0,1
    #pragma unroll
    for (int st = 0; st < NST - 1; st++) {
        const uint32_t so = st * 8192;
        #pragma unroll
        for (int j = 0; j < 4; j++) {
            cpa16(saoff[j] + so, agp + st * 32 + j * 4);
            cpa16(sboff[j] + so, bgp + st * 32 + j * 4);
        }
        CP_COMMIT();
    }

    int sbuf = 0;
    for (int it = 0; it < KTILES; it++) {
        CP_WAIT1();
        __syncthreads();

        const int nst = it + NST - 1;
        if (nst < KTILES) {
            const int nb = (sbuf + 2 >= NST) ? sbuf + 2 - NST : sbuf + 2;
            const uint32_t so = nb * 8192;
            #pragma unroll
            for (int j = 0; j < 4; j++) {
                cpa16(saoff[j] + so, agp + nst * 32 + j * 4);
                cpa16(sboff[j] + so, bgp + nst * 32 + j * 4);
            }
        }
        CP_COMMIT();

        const uint32_t so = sbuf * 8192;
        #pragma unroll
        for (int h = 0; h < 4; h++) {
            uint32_t af[2][4], bfr[2][4];
            ldm_x4(af[0][0], af[0][1], af[0][2], af[0][3], aaddr[0][h] + so);
            ldm_x4(af[1][0], af[1][1], af[1][2], af[1][3], aaddr[1][h] + so);
            ldm_x4(bfr[0][0], bfr[0][1], bfr[0][2], bfr[0][3], baddr[0][h] + so);
            ldm_x4(bfr[1][0], bfr[1][1], bfr[1][2], bfr[1][3], baddr[1][h] + so);
            // unbiased round-to-nearest-tf32 (kills truncation bias)
            #pragma unroll
            for (int f = 0; f < 2; f++)
                #pragma unroll
                for (int i = 0; i < 4; i++) af[f][i] = RN_TF32(af[f][i]);
            #pragma unroll
            for (int g = 0; g < 2; g++)
                #pragma unroll
                for (int i = 0; i < 4; i++) bfr[g][i] = RN_TF32(bfr[g][i]);
            #pragma unroll
            for (int f = 0; f < 2; f++) {
                #pragma unroll
                for (int g = 0; g < 2; g++) {
                    mma168_tf32(acc[f][2 * g + 0], af[f], &bfr[g][0]);
                    mma168_tf32(acc[f][2 * g + 1], af[f], &bfr[g][2]);
                }
            }
        }
        sbuf = (sbuf + 1 >= NST) ? 0 : sbuf + 1;
    }

    // epilogue: add bias, store fp32
    const int tg = lane >> 2;
    const int tc = (lane & 3) * 2;
    #pragma unroll
    for (int f = 0; f < 2; f++) {
        const int rbase = row0 + warp_m * 32 + f * 16 + tg;
        #pragma unroll
        for (int g = 0; g < 4; g++) {
            const int c = col0 + warp_n * 32 + g * 8 + tc;
            const float b0 = bias[c], b1 = bias[c + 1];
            float2 v0 = { acc[f][g][0] + b0, acc[f][g][1] + b1 };
            float2 v1 = { acc[f][g][2] + b0, acc[f][g][3] + b1 };
            *(float2*)&Cw[(size_t)rbase * D + c]       = v0;
            *(float2*)&Cw[(size_t)(rbase + 8) * D + c] = v1;
        }
    }
}

// ---------------------------------------------------------------------------
// Attention via rank-13 Taylor factorization of exp(q*k/16).
// 256 CTAs x 8 warps (one warp per token). Lane owns 8 contiguous elements.
// ---------------------------------------------------------------------------
__global__ __launch_bounds__(256) void attn_kernel(float* __restrict__ out)
{
    const int lane = threadIdx.x & 31;
    const int t = blockIdx.x * 8 + (threadIdx.x >> 5);
    const int base = t * D;
    const int eb = base + lane * 8;
    const float s = 1.0f / 16.0f;

    float4 k4a = *(const float4*)&g_K[eb];
    float4 k4b = *(const float4*)&g_K[eb + 4];
    float4 v4a = *(const float4*)&g_V[eb];
    float4 v4b = *(const float4*)&g_V[eb + 4];
    float4 q4a = *(const float4*)&g_Q[eb];
    float4 q4b = *(const float4*)&g_Q[eb + 4];

    float kv[8] = { k4a.x * s, k4a.y * s, k4a.z * s, k4a.w * s,
                    k4b.x * s, k4b.y * s, k4b.z * s, k4b.w * s };
    float vv[8] = { v4a.x, v4a.y, v4a.z, v4a.w, v4b.x, v4b.y, v4b.z, v4b.w };
    float qv[8] = { q4a.x, q4a.y, q4a.z, q4a.w, q4b.x, q4b.y, q4b.z, q4b.w };

    float m[13], M[13];
    #pragma unroll
    for (int n = 0; n < 13; n++) { m[n] = 0.f; M[n] = 0.f; }
    #pragma unroll
    for (int u = 0; u < 8; u++) {
        const float k1 = kv[u], v1 = vv[u];
        M[0] += v1;
        float kp = k1;
        m[1] += kp; M[1] += kp * v1;
        #pragma unroll
        for (int n = 2; n <= 12; n++) {
            kp *= k1;
            m[n] += kp;
            M[n] += kp * v1;
        }
    }
    m[0] = 8.0f;

    #pragma unroll
    for (int off = 16; off; off >>= 1) {
        #pragma unroll
        for (int n = 0; n < 13; n++) {
            m[n] += __shfl_xor_sync(0xFFFFFFFFu, m[n], off);
            M[n] += __shfl_xor_sync(0xFFFFFFFFu, M[n], off);
        }
    }

    const float invf[13] = {
        1.f, 1.f, 0.5f, 1.f/6.f, 1.f/24.f, 1.f/120.f, 1.f/720.f,
        1.f/5040.f, 1.f/40320.f, 1.f/362880.f, 1.f/3628800.f,
        1.f/39916800.f, 1.f/479001600.f };
    #pragma unroll
    for (int n = 2; n < 13; n++) { m[n] *= invf[n]; M[n] *= invf[n]; }

    float res[8];
    #pragma unroll
    for (int u = 0; u < 8; u++) {
        const float q = qv[u];
        float num = M[12], den = m[12];
        #pragma unroll
        for (int n = 11; n >= 0; n--) {
            num = num * q + M[n];
            den = den * q + m[n];
        }
        res[u] = __fdividef(num, den);
    }
    *(float4*)&out[eb]     = make_float4(res[0], res[1], res[2], res[3]);
    *(float4*)&out[eb + 4] = make_float4(res[4], res[5], res[6], res[7]);
}

// ---------------------------------------------------------------------------
// Launch. Inputs: x, Wq, bq, Wk, bk, Wv, bv. Output fp32 [2,1024,256].
// ---------------------------------------------------------------------------
extern "C" void kernel_launch(void* const* d_in, const int* in_sizes, int n_in,
                              void* d_out, int out_size)
{
    const float* x  = (const float*)d_in[0];
    const float* Wq = (const float*)d_in[1];
    const float* bq = (const float*)d_in[2];
    const float* Wk = (const float*)d_in[3];
    const float* bk = (const float*)d_in[4];
    const float* Wv = (const float*)d_in[5];
    const float* bv = (const float*)d_in[6];
    float* out = (float*)d_out;

    dim3 ggrid(BT / 64, D / 64, 3);   // 32 x 4 x 3 = 384 CTAs
    mma_gemm<<<ggrid, 128>>>(x, Wq, Wk, Wv, bq, bk, bv);
    attn_kernel<<<BT / 8, 256>>>(out);
}

// round 14
// speedup vs baseline: 1.6754x; 1.1847x over previous
#include <cuda_runtime.h>
#include <cstdint>

#define D 256
#define BT 2048   // B*T
#define NST 3     // cp.async pipeline stages
#define KTILES 8  // K=256 in 32-float tiles

// Scratch (static device globals — no allocation).
__device__ float g_Q[BT * D];
__device__ float g_K[BT * D];
__device__ float g_V[BT * D];

// ---------------------------------------------------------------------------
// helpers
// ---------------------------------------------------------------------------
__device__ __forceinline__ uint32_t smem_u32(const void* p) {
    uint32_t a;
    asm("{ .reg .u64 t; cvta.to.shared.u64 t, %1; cvt.u32.u64 %0, t; }"
        : "=r"(a) : "l"(p));
    return a;
}
__device__ __forceinline__ void ldm_x4(uint32_t& r0, uint32_t& r1,
                                       uint32_t& r2, uint32_t& r3, uint32_t a) {
    asm volatile("ldmatrix.sync.aligned.m8n8.x4.shared.b16 {%0,%1,%2,%3}, [%4];"
                 : "=r"(r0), "=r"(r1), "=r"(r2), "=r"(r3) : "r"(a));
}
// m16n8k8 TF32 MMA. A frag 4 regs, B frag 2 regs, C/D 4 f32.
__device__ __forceinline__ void mma168_tf32(float* c, const uint32_t* a,
                                            const uint32_t* b) {
    asm volatile(
        "mma.sync.aligned.m16n8k8.row.col.f32.tf32.tf32.f32 "
        "{%0,%1,%2,%3}, {%4,%5,%6,%7}, {%8,%9}, {%0,%1,%2,%3};"
        : "+f"(c[0]), "+f"(c[1]), "+f"(c[2]), "+f"(c[3])
        : "r"(a[0]), "r"(a[1]), "r"(a[2]), "r"(a[3]), "r"(b[0]), "r"(b[1]));
}
__device__ __forceinline__ void cpa16(uint32_t s, const void* g) {
    asm volatile("cp.async.cg.shared.global [%0], [%1], 16;"
                 :: "r"(s), "l"(g) : "memory");
}
#define CP_COMMIT() asm volatile("cp.async.commit_group;" ::: "memory")
#define CP_WAIT1()  asm volatile("cp.async.wait_group 1;" ::: "memory")

// Round f32 bits to nearest tf32 (13 low mantissa bits): +0x1000, HW truncates.
#define RN_TF32(r) ((r) + 0x1000u)

// 128B rows, 8 x 16B chunks, full XOR swizzle: chunk ^= row&7.
#define SWOFF2(row, c) ((row) * 128 + ((((c) ^ ((row) & 7))) << 4))

// ---------------------------------------------------------------------------
// TF32 mma.sync GEMM on RAW fp32 inputs (no conversion pass).
//   C[64,64] tile = x[64,256] @ W[64,256]^T + bias
// 256 threads / 8 warps, warp tile 16(M) x 32(N) (warp grid 4x2) for
// 2x scheduler slack vs the 4-warp version (stall-bound, not tensor-bound).
// K-step 32 floats (128B rows), 3-stage cp.async. RN-rounding to tf32 in
// registers (unbiased). Grid 32 x 4 x 3 = 384 CTAs (~3072 warps chip-wide).
// ---------------------------------------------------------------------------
__global__ __launch_bounds__(256) void mma_gemm(
    const float* __restrict__ X,
    const float* __restrict__ Wq, const float* __restrict__ Wk,
    const float* __restrict__ Wv,
    const float* __restrict__ bq, const float* __restrict__ bk,
    const float* __restrict__ bv)
{
    __shared__ __align__(16) char sA[NST][64 * 128];   // 24KB
    __shared__ __align__(16) char sB[NST][64 * 128];   // 24KB

    const int tid  = threadIdx.x;
    const int lane = tid & 31;
    const int wid  = tid >> 5;
    const int warp_m = wid & 3;          // 4 x m16 = 64 M
    const int warp_n = wid >> 2;         // 2 x n32 = 64 N

    const int row0 = blockIdx.x * 64;
    const int col0 = blockIdx.y * 64;
    const int z    = blockIdx.z;
    const float* Wg   = (z == 0) ? Wq : (z == 1) ? Wk : Wv;
    const float* bias = (z == 0) ? bq : (z == 1) ? bk : bv;
    float* Cw = (z == 0) ? g_Q : (z == 1) ? g_K : g_V;

    // loader: thread -> (row, 2 x 16B chunks); k-tile = 32 floats = 8 chunks
    const int lrow  = tid >> 2;          // 0..63
    const int cbase = (tid & 3) * 2;     // 0,2,4,6
    const float* agp = X  + (size_t)(row0 + lrow) * D + cbase * 4;
    const float* bgp = Wg + (size_t)(col0 + lrow) * D + cbase * 4;
    const uint32_t sA_base = smem_u32(sA);
    const uint32_t sB_base = smem_u32(sB);
    uint32_t saoff[2], sboff[2];
    #pragma unroll
    for (int j = 0; j < 2; j++) {
        saoff[j] = sA_base + SWOFF2(lrow, cbase + j);
        sboff[j] = sB_base + SWOFF2(lrow, cbase + j);
    }

    // ldmatrix fragment addresses over 4 k8-steps per 128B row.
    // A: 1 frag (m16); B: 2 frag groups (2 x n16).
    uint32_t aaddr[4], baddr[2][4];
    {
        const int m = lane >> 3;
        const int ar  = ((m & 1) << 3) + (lane & 7);
        const int akc = m >> 1;
        const int bn  = ((m >> 1) << 3) + (lane & 7);
        const int bkc = m & 1;
        {
            const int row = warp_m * 16 + ar;
            #pragma unroll
            for (int h = 0; h < 4; h++)
                aaddr[h] = sA_base + SWOFF2(row, akc + 2 * h);
        }
        #pragma unroll
        for (int g = 0; g < 2; g++) {
            const int row = warp_n * 32 + g * 16 + bn;
            #pragma unroll
            for (int h = 0; h < 4; h++)
                baddr[g][h] = sB_base + SWOFF2(row, bkc + 2 * h);
        }
    }

    float acc[4][4];                      // [n8-group][quad]
    #pragma unroll
    for (int g = 0; g < 4; g++)
        #pragma unroll
        for (int i = 0; i < 4; i++) acc[g][i] = 0.f;

    // prologue: stages 0,1
    #pragma unroll
    for (int st = 0; st < NST - 1; st++) {
        const uint32_t so = st * 8192;
        #pragma unroll
        for (int j = 0; j < 2; j++) {
            cpa16(saoff[j] + so, agp + st * 32 + j * 4);
            cpa16(sboff[j] + so, bgp + st * 32 + j * 4);
        }
        CP_COMMIT();
    }

    int sbuf = 0;
    for (int it = 0; it < KTILES; it++) {
        CP_WAIT1();
        __syncthreads();

        const int nst = it + NST - 1;
        if (nst < KTILES) {
            const int nb = (sbuf + 2 >= NST) ? sbuf + 2 - NST : sbuf + 2;
            const uint32_t so = nb * 8192;
            #pragma unroll
            for (int j = 0; j < 2; j++) {
                cpa16(saoff[j] + so, agp + nst * 32 + j * 4);
                cpa16(sboff[j] + so, bgp + nst * 32 + j * 4);
            }
        }
        CP_COMMIT();

        const uint32_t so = sbuf * 8192;
        #pragma unroll
        for (int h = 0; h < 4; h++) {
            uint32_t af[4], bfr[2][4];
            ldm_x4(af[0], af[1], af[2], af[3], aaddr[h] + so);
            ldm_x4(bfr[0][0], bfr[0][1], bfr[0][2], bfr[0][3], baddr[0][h] + so);
            ldm_x4(bfr[1][0], bfr[1][1], bfr[1][2], bfr[1][3], baddr[1][h] + so);
            // unbiased round-to-nearest-tf32
            #pragma unroll
            for (int i = 0; i < 4; i++) af[i] = RN_TF32(af[i]);
            #pragma unroll
            for (int g = 0; g < 2; g++)
                #pragma unroll
                for (int i = 0; i < 4; i++) bfr[g][i] = RN_TF32(bfr[g][i]);
            #pragma unroll
            for (int g = 0; g < 2; g++) {
                mma168_tf32(acc[2 * g + 0], af, &bfr[g][0]);
                mma168_tf32(acc[2 * g + 1], af, &bfr[g][2]);
            }
        }
        sbuf = (sbuf + 1 >= NST) ? 0 : sbuf + 1;
    }

    // epilogue: add bias, store fp32 (warp tile m16 x n32)
    const int tg = lane >> 2;
    const int tc = (lane & 3) * 2;
    const int rbase = row0 + warp_m * 16 + tg;
    #pragma unroll
    for (int g = 0; g < 4; g++) {
        const int c = col0 + warp_n * 32 + g * 8 + tc;
        const float b0 = bias[c], b1 = bias[c + 1];
        float2 v0 = { acc[g][0] + b0, acc[g][1] + b1 };
        float2 v1 = { acc[g][2] + b0, acc[g][3] + b1 };
        *(float2*)&Cw[(size_t)rbase * D + c]       = v0;
        *(float2*)&Cw[(size_t)(rbase + 8) * D + c] = v1;
    }
}

// ---------------------------------------------------------------------------
// Attention via rank-13 Taylor factorization of exp(q*k/16).
// 256 CTAs x 8 warps (one warp per token). Lane owns 8 contiguous elements.
// ---------------------------------------------------------------------------
__global__ __launch_bounds__(256) void attn_kernel(float* __restrict__ out)
{
    const int lane = threadIdx.x & 31;
    const int t = blockIdx.x * 8 + (threadIdx.x >> 5);
    const int base = t * D;
    const int eb = base + lane * 8;
    const float s = 1.0f / 16.0f;

    float4 k4a = *(const float4*)&g_K[eb];
    float4 k4b = *(const float4*)&g_K[eb + 4];
    float4 v4a = *(const float4*)&g_V[eb];
    float4 v4b = *(const float4*)&g_V[eb + 4];
    float4 q4a = *(const float4*)&g_Q[eb];
    float4 q4b = *(const float4*)&g_Q[eb + 4];

    float kv[8] = { k4a.x * s, k4a.y * s, k4a.z * s, k4a.w * s,
                    k4b.x * s, k4b.y * s, k4b.z * s, k4b.w * s };
    float vv[8] = { v4a.x, v4a.y, v4a.z, v4a.w, v4b.x, v4b.y, v4b.z, v4b.w };
    float qv[8] = { q4a.x, q4a.y, q4a.z, q4a.w, q4b.x, q4b.y, q4b.z, q4b.w };

    float m[13], M[13];
    #pragma unroll
    for (int n = 0; n < 13; n++) { m[n] = 0.f; M[n] = 0.f; }
    #pragma unroll
    for (int u = 0; u < 8; u++) {
        const float k1 = kv[u], v1 = vv[u];
        M[0] += v1;
        float kp = k1;
        m[1] += kp; M[1] += kp * v1;
        #pragma unroll
        for (int n = 2; n <= 12; n++) {
            kp *= k1;
            m[n] += kp;
            M[n] += kp * v1;
        }
    }
    m[0] = 8.0f;

    #pragma unroll
    for (int off = 16; off; off >>= 1) {
        #pragma unroll
        for (int n = 0; n < 13; n++) {
            m[n] += __shfl_xor_sync(0xFFFFFFFFu, m[n], off);
            M[n] += __shfl_xor_sync(0xFFFFFFFFu, M[n], off);
        }
    }

    const float invf[13] = {
        1.f, 1.f, 0.5f, 1.f/6.f, 1.f/24.f, 1.f/120.f, 1.f/720.f,
        1.f/5040.f, 1.f/40320.f, 1.f/362880.f, 1.f/3628800.f,
        1.f/39916800.f, 1.f/479001600.f };
    #pragma unroll
    for (int n = 2; n < 13; n++) { m[n] *= invf[n]; M[n] *= invf[n]; }

    float res[8];
    #pragma unroll
    for (int u = 0; u < 8; u++) {
        const float q = qv[u];
        float num = M[12], den = m[12];
        #pragma unroll
        for (int n = 11; n >= 0; n--) {
            num = num * q + M[n];
            den = den * q + m[n];
        }
        res[u] = __fdividef(num, den);
    }
    *(float4*)&out[eb]     = make_float4(res[0], res[1], res[2], res[3]);
    *(float4*)&out[eb + 4] = make_float4(res[4], res[5], res[6], res[7]);
}

// ---------------------------------------------------------------------------
// Launch. Inputs: x, Wq, bq, Wk, bk, Wv, bv. Output fp32 [2,1024,256].
// ---------------------------------------------------------------------------
extern "C" void kernel_launch(void* const* d_in, const int* in_sizes, int n_in,
                              void* d_out, int out_size)
{
    const float* x  = (const float*)d_in[0];
    const float* Wq = (const float*)d_in[1];
    const float* bq = (const float*)d_in[2];
    const float* Wk = (const float*)d_in[3];
    const float* bk = (const float*)d_in[4];
    const float* Wv = (const float*)d_in[5];
    const float* bv = (const float*)d_in[6];
    float* out = (float*)d_out;

    dim3 ggrid(BT / 64, D / 64, 3);   // 32 x 4 x 3 = 384 CTAs
    mma_gemm<<<ggrid, 256>>>(x, Wq, Wk, Wv, bq, bk, bv);
    attn_kernel<<<BT / 8, 256>>>(out);
}